// round 6
// baseline (speedup 1.0000x reference)
#include <cuda_runtime.h>
#include <cuda_fp16.h>
#include <cstdint>

// Problem constants
#define NB   32      // batch
#define NN   1024    // nodes per graph
#define NF   128     // in features
#define NH   128     // hidden features

// fp32 scratch for support = x @ W (static -> allocation-guard safe)
__device__ float g_support[(size_t)NB * NN * NH];   // 16 MB

// ===========================================================================
// PTX helpers (baseline sm_80-class instructions -> compile on compute_103)
// ===========================================================================
__device__ __forceinline__ uint32_t smem_to_u32(const void* p) {
    uint32_t a;
    asm("{ .reg .u64 t; cvta.to.shared.u64 t, %1; cvt.u32.u64 %0, t; }" : "=r"(a) : "l"(p));
    return a;
}

#define LDSM4(R, addr) \
    asm volatile("ldmatrix.sync.aligned.m8n8.x4.shared.b16 {%0,%1,%2,%3}, [%4];" \
        : "=r"((R)[0]), "=r"((R)[1]), "=r"((R)[2]), "=r"((R)[3]) : "r"(addr))

#define LDSM4T(R, addr) \
    asm volatile("ldmatrix.sync.aligned.m8n8.x4.trans.shared.b16 {%0,%1,%2,%3}, [%4];" \
        : "=r"((R)[0]), "=r"((R)[1]), "=r"((R)[2]), "=r"((R)[3]) : "r"(addr))

#define MMA16816(C, A, b0, b1) \
    asm volatile("mma.sync.aligned.m16n8k16.row.col.f32.f16.f16.f32 " \
        "{%0,%1,%2,%3},{%4,%5,%6,%7},{%8,%9},{%0,%1,%2,%3};" \
        : "+f"((C)[0]), "+f"((C)[1]), "+f"((C)[2]), "+f"((C)[3]) \
        : "r"((A)[0]), "r"((A)[1]), "r"((A)[2]), "r"((A)[3]), "r"(b0), "r"(b1))

__device__ __forceinline__ uint32_t pack_h2(__half a, __half b) {
    __half2 t = __halves2half2(a, b);
    return *reinterpret_cast<uint32_t*>(&t);
}

// fp32 -> (hi fp16, lo fp16) split of a float4
__device__ __forceinline__ void split4(float4 v, uint2& hu, uint2& lu) {
    __half h0 = __float2half_rn(v.x), h1 = __float2half_rn(v.y);
    __half h2 = __float2half_rn(v.z), h3 = __float2half_rn(v.w);
    __half l0 = __float2half_rn(v.x - __half2float(h0));
    __half l1 = __float2half_rn(v.y - __half2float(h1));
    __half l2 = __float2half_rn(v.z - __half2float(h2));
    __half l3 = __float2half_rn(v.w - __half2float(h3));
    hu.x = pack_h2(h0, h1); hu.y = pack_h2(h2, h3);
    lu.x = pack_h2(l0, l1); lu.y = pack_h2(l2, l3);
}

// ===========================================================================
// Split-fp16 HMMA GEMM: C = [relu(] A(fp32, MxK) @ B(fp32, Kx128) [+bias)]
//   CTA: 128x128 tile, 512 threads = 16 warps (4m x 4n), warp tile 32x32.
//   BK=32, double-buffered fp16 smem, single-sync pipelined schedule:
//     storeStage(ch+1) issued alongside compute(ch) (different buffers),
//     then load(ch+2) into regs, one __syncthreads per iteration.
//   2 CTAs/SM (launch_bounds 512,2) -> whole grid (256 CTAs) in one wave.
//   3-pass error-compensated fp16: Ah*Bh + Ah*Bl + Al*Bh, fp32 accumulate.
// ===========================================================================
#define RSA   80        // A smem row stride bytes (32+8 halves)
#define RSB   272       // B smem row stride bytes (128+8 halves)
#define OAH   0
#define OAL   10240     // 128*80
#define OBH   20480
#define OBL   29184     // +32*272
#define STAGE 37888
#define SMEMB (2*STAGE + 512)

template <int K, bool BIAS_RELU>
__global__ __launch_bounds__(512, 2)
void mma_gemm_kernel(const float* __restrict__ A, long lda, long strideAb,
                     const float* __restrict__ B, long strideBb,
                     float* __restrict__ C, long strideCb,
                     const float* __restrict__ bias)
{
    extern __shared__ char smem[];
    constexpr int NCH = K / 32;

    const int tid = threadIdx.x;
    const int l   = tid & 31;
    const int wid = tid >> 5;      // 0..15
    const int wm  = wid >> 2;      // 0..3
    const int wn  = wid & 3;       // 0..3

    const float* Ag = A + (size_t)blockIdx.y * strideAb + (size_t)blockIdx.x * 128 * lda;
    const float* Bg = B + (size_t)blockIdx.y * strideBb;
    float*       Cg = C + (size_t)blockIdx.y * strideCb + (size_t)blockIdx.x * 128 * NH;

    float* bias_s = reinterpret_cast<float*>(smem + 2 * STAGE);
    if (BIAS_RELU && tid < NH) bias_s[tid] = bias[tid];

    const uint32_t sb = smem_to_u32(smem);

    float c[2][4][4];               // [m-atom 16][n8 j][quad]
    #pragma unroll
    for (int i = 0; i < 2; i++)
        #pragma unroll
        for (int j = 0; j < 4; j++)
            #pragma unroll
            for (int q = 0; q < 4; q++) c[i][j][q] = 0.0f;

    float4 pa[2], pb[2];            // register prefetch: 128x32 A + 32x128 B chunk

    auto loadA = [&](int k0) {
        #pragma unroll
        for (int s = 0; s < 2; s++) {
            int f = s * 512 + tid;
            int r = f >> 3, c4 = f & 7;
            pa[s] = *reinterpret_cast<const float4*>(Ag + (size_t)r * lda + k0 + c4 * 4);
        }
    };
    auto loadB = [&](int k0) {
        #pragma unroll
        for (int s = 0; s < 2; s++) {
            int f = s * 512 + tid;
            int r = f >> 5, c4 = f & 31;
            pb[s] = *reinterpret_cast<const float4*>(Bg + (size_t)(k0 + r) * NH + c4 * 4);
        }
    };
    auto storeStage = [&](int buf) {
        char* st = smem + buf * STAGE;
        #pragma unroll
        for (int s = 0; s < 2; s++) {
            int f = s * 512 + tid;
            int r = f >> 3, c4 = f & 7;
            uint2 hu, lu; split4(pa[s], hu, lu);
            *reinterpret_cast<uint2*>(st + OAH + r * RSA + c4 * 8) = hu;
            *reinterpret_cast<uint2*>(st + OAL + r * RSA + c4 * 8) = lu;
        }
        #pragma unroll
        for (int s = 0; s < 2; s++) {
            int f = s * 512 + tid;
            int r = f >> 5, c4 = f & 31;
            uint2 hu, lu; split4(pb[s], hu, lu);
            *reinterpret_cast<uint2*>(st + OBH + r * RSB + c4 * 8) = hu;
            *reinterpret_cast<uint2*>(st + OBL + r * RSB + c4 * 8) = lu;
        }
    };
    auto compute = [&](int buf) {
        const uint32_t stg = sb + buf * STAGE;
        #pragma unroll
        for (int ks = 0; ks < 2; ks++) {
            uint32_t ar = stg + OAH + (uint32_t)(wm * 32 + (l & 15)) * RSA + ks * 32 + (l >> 4) * 16;
            uint32_t ah0[4], ah1[4], al0[4], al1[4];
            LDSM4(ah0, ar);
            LDSM4(ah1, ar + 16 * RSA);
            LDSM4(al0, ar + (OAL - OAH));
            LDSM4(al1, ar + (OAL - OAH) + 16 * RSA);
            #pragma unroll
            for (int jp = 0; jp < 2; jp++) {   // two n16 groups -> 4 n8 atoms
                uint32_t br = stg + OBH + (uint32_t)(ks * 16 + (l & 15)) * RSB
                            + (uint32_t)(wn * 32 + jp * 16 + (l >> 4) * 8) * 2;
                uint32_t bh[4], bl[4];
                LDSM4T(bh, br);
                LDSM4T(bl, br + (OBL - OBH));
                #pragma unroll
                for (int jj = 0; jj < 2; jj++) {
                    const int j = jp * 2 + jj;
                    MMA16816(c[0][j], ah0, bh[2*jj], bh[2*jj+1]);   // hh
                    MMA16816(c[1][j], ah1, bh[2*jj], bh[2*jj+1]);
                    MMA16816(c[0][j], ah0, bl[2*jj], bl[2*jj+1]);   // hl
                    MMA16816(c[1][j], ah1, bl[2*jj], bl[2*jj+1]);
                    MMA16816(c[0][j], al0, bh[2*jj], bh[2*jj+1]);   // lh
                    MMA16816(c[1][j], al1, bh[2*jj], bh[2*jj+1]);
                }
            }
        }
    };

    // -------- pipeline: one __syncthreads per iteration --------
    loadA(0); loadB(0);
    storeStage(0);
    if (NCH > 1) { loadA(32); loadB(32); }
    __syncthreads();

    for (int ch = 0; ch < NCH; ch++) {
        // store next chunk (regs -> other buffer) interleaved with this MMA burst
        if (ch + 1 < NCH) storeStage((ch + 1) & 1);
        compute(ch & 1);
        if (ch + 2 < NCH) { loadA((ch + 2) * 32); loadB((ch + 2) * 32); }
        __syncthreads();
    }

    // -------- epilogue --------
    #pragma unroll
    for (int i = 0; i < 2; i++) {
        const int r0 = wm * 32 + i * 16 + (l >> 2);
        #pragma unroll
        for (int j = 0; j < 4; j++) {
            const int col = wn * 32 + j * 8 + (l & 3) * 2;
            float2 v0 = make_float2(c[i][j][0], c[i][j][1]);
            float2 v1 = make_float2(c[i][j][2], c[i][j][3]);
            if (BIAS_RELU) {
                const float b0 = bias_s[col], b1 = bias_s[col + 1];
                v0.x = fmaxf(v0.x + b0, 0.0f); v0.y = fmaxf(v0.y + b1, 0.0f);
                v1.x = fmaxf(v1.x + b0, 0.0f); v1.y = fmaxf(v1.y + b1, 0.0f);
            }
            *reinterpret_cast<float2*>(Cg + (size_t)r0 * NH + col)       = v0;
            *reinterpret_cast<float2*>(Cg + (size_t)(r0 + 8) * NH + col) = v1;
        }
    }
}

// ===========================================================================
// Launch: GEMM-1 (x@W -> support, fp32) then GEMM-2 (relu(adj@support + b))
// ===========================================================================
extern "C" void kernel_launch(void* const* d_in, const int* in_sizes, int n_in,
                              void* d_out, int out_size)
{
    const float* x   = (const float*)d_in[0];
    const float* adj = (const float*)d_in[1];
    const float* W   = (const float*)d_in[2];
    const float* b   = (const float*)d_in[3];
    float* out = (float*)d_out;

    float* support = nullptr;
    cudaGetSymbolAddress((void**)&support, g_support);

    cudaFuncSetAttribute(mma_gemm_kernel<NF, false>,
                         cudaFuncAttributeMaxDynamicSharedMemorySize, SMEMB);
    cudaFuncSetAttribute(mma_gemm_kernel<NN, true>,
                         cudaFuncAttributeMaxDynamicSharedMemorySize, SMEMB);

    // GEMM-1: support = x @ W    (x as flat [32768, 128], W shared)
    mma_gemm_kernel<NF, false><<<dim3(NB * NN / 128, 1), 512, SMEMB>>>(
        x, NF, 0L, W, 0L, support, 0L, nullptr);

    // GEMM-2: out = relu(adj @ support + b)
    mma_gemm_kernel<NN, true><<<dim3(NN / 128, NB), 512, SMEMB>>>(
        adj, NN, (long)NN * NN, support, (long)NN * NH, out, (long)NN * NH, b);
}

// round 8
// speedup vs baseline: 1.0914x; 1.0914x over previous
#include <cuda_runtime.h>
#include <cuda_fp16.h>
#include <cstdint>

// Problem constants
#define NB   32      // batch
#define NN   1024    // nodes per graph
#define NF   128     // in features
#define NH   128     // hidden features

// fp32 scratch for support = x @ W (static -> allocation-guard safe)
__device__ float g_support[(size_t)NB * NN * NH];   // 16 MB

// ===========================================================================
// PTX helpers (baseline sm_80-class instructions -> compile on compute_103)
// ===========================================================================
__device__ __forceinline__ uint32_t smem_to_u32(const void* p) {
    uint32_t a;
    asm("{ .reg .u64 t; cvta.to.shared.u64 t, %1; cvt.u32.u64 %0, t; }" : "=r"(a) : "l"(p));
    return a;
}

#define LDSM4(R, addr) \
    asm volatile("ldmatrix.sync.aligned.m8n8.x4.shared.b16 {%0,%1,%2,%3}, [%4];" \
        : "=r"((R)[0]), "=r"((R)[1]), "=r"((R)[2]), "=r"((R)[3]) : "r"(addr))

#define LDSM4T(R, addr) \
    asm volatile("ldmatrix.sync.aligned.m8n8.x4.trans.shared.b16 {%0,%1,%2,%3}, [%4];" \
        : "=r"((R)[0]), "=r"((R)[1]), "=r"((R)[2]), "=r"((R)[3]) : "r"(addr))

#define MMA16816(C, A, b0, b1) \
    asm volatile("mma.sync.aligned.m16n8k16.row.col.f32.f16.f16.f32 " \
        "{%0,%1,%2,%3},{%4,%5,%6,%7},{%8,%9},{%0,%1,%2,%3};" \
        : "+f"((C)[0]), "+f"((C)[1]), "+f"((C)[2]), "+f"((C)[3]) \
        : "r"((A)[0]), "r"((A)[1]), "r"((A)[2]), "r"((A)[3]), "r"(b0), "r"(b1))

__device__ __forceinline__ uint32_t pack_h2(__half a, __half b) {
    __half2 t = __halves2half2(a, b);
    return *reinterpret_cast<uint32_t*>(&t);
}

// fp32 -> (hi fp16, lo fp16) split of a float4
__device__ __forceinline__ void split4(float4 v, uint2& hu, uint2& lu) {
    __half h0 = __float2half_rn(v.x), h1 = __float2half_rn(v.y);
    __half h2 = __float2half_rn(v.z), h3 = __float2half_rn(v.w);
    __half l0 = __float2half_rn(v.x - __half2float(h0));
    __half l1 = __float2half_rn(v.y - __half2float(h1));
    __half l2 = __float2half_rn(v.z - __half2float(h2));
    __half l3 = __float2half_rn(v.w - __half2float(h3));
    hu.x = pack_h2(h0, h1); hu.y = pack_h2(h2, h3);
    lu.x = pack_h2(l0, l1); lu.y = pack_h2(l2, l3);
}

// ===========================================================================
// Split-fp16 HMMA GEMM: C = [relu(] A(fp32, MxK) @ B(fp32, Kx128) [+bias)]
//   CTA: 128x128 tile, 256 threads = 8 warps (4m x 2n), warp tile 32x64.
//   BK=32, double-buffered fp16 smem.
//   Single-sync pipelined schedule: storeStage(ch+1) (into the buffer
//   compute isn't reading) issued back-to-back with compute(ch), so the
//   CVT/STS stream of one warp dual-issues under the MMA stream of the
//   other warp on each SMSP. Then load(ch+2) into regs, one sync.
//   No launch_bounds occupancy cap: regs ~184, 1 CTA/SM, NO SPILLS.
//   3-pass error-compensated fp16: Ah*Bh + Ah*Bl + Al*Bh, fp32 accumulate.
// ===========================================================================
#define RSA   80        // A smem row stride bytes (32+8 halves)
#define RSB   272       // B smem row stride bytes (128+8 halves)
#define OAH   0
#define OAL   10240     // 128*80
#define OBH   20480
#define OBL   29184     // +32*272
#define STAGE 37888
#define SMEMB (2*STAGE + 512)

template <int K, bool BIAS_RELU>
__global__ __launch_bounds__(256, 1)
void mma_gemm_kernel(const float* __restrict__ A, long lda, long strideAb,
                     const float* __restrict__ B, long strideBb,
                     float* __restrict__ C, long strideCb,
                     const float* __restrict__ bias)
{
    extern __shared__ char smem[];
    constexpr int NCH = K / 32;

    const int tid = threadIdx.x;
    const int l   = tid & 31;
    const int wid = tid >> 5;
    const int wm  = wid >> 1;      // 0..3
    const int wn  = wid & 1;       // 0..1

    const float* Ag = A + (size_t)blockIdx.y * strideAb + (size_t)blockIdx.x * 128 * lda;
    const float* Bg = B + (size_t)blockIdx.y * strideBb;
    float*       Cg = C + (size_t)blockIdx.y * strideCb + (size_t)blockIdx.x * 128 * NH;

    float* bias_s = reinterpret_cast<float*>(smem + 2 * STAGE);
    if (BIAS_RELU && tid < NH) bias_s[tid] = bias[tid];

    const uint32_t sb = smem_to_u32(smem);

    float c[2][8][4];
    #pragma unroll
    for (int i = 0; i < 2; i++)
        #pragma unroll
        for (int j = 0; j < 8; j++)
            #pragma unroll
            for (int q = 0; q < 4; q++) c[i][j][q] = 0.0f;

    float4 pa[4], pb[4];    // register prefetch for one 128x32 A + 32x128 B chunk

    auto loadA = [&](int k0) {
        #pragma unroll
        for (int s = 0; s < 4; s++) {
            int f = s * 256 + tid;
            int r = f >> 3, c4 = f & 7;
            pa[s] = *reinterpret_cast<const float4*>(Ag + (size_t)r * lda + k0 + c4 * 4);
        }
    };
    auto loadB = [&](int k0) {
        #pragma unroll
        for (int s = 0; s < 4; s++) {
            int f = s * 256 + tid;
            int r = f >> 5, c4 = f & 31;
            pb[s] = *reinterpret_cast<const float4*>(Bg + (size_t)(k0 + r) * NH + c4 * 4);
        }
    };
    auto storeStage = [&](int buf) {
        char* st = smem + buf * STAGE;
        #pragma unroll
        for (int s = 0; s < 4; s++) {
            int f = s * 256 + tid;
            int r = f >> 3, c4 = f & 7;
            uint2 hu, lu; split4(pa[s], hu, lu);
            *reinterpret_cast<uint2*>(st + OAH + r * RSA + c4 * 8) = hu;
            *reinterpret_cast<uint2*>(st + OAL + r * RSA + c4 * 8) = lu;
        }
        #pragma unroll
        for (int s = 0; s < 4; s++) {
            int f = s * 256 + tid;
            int r = f >> 5, c4 = f & 31;
            uint2 hu, lu; split4(pb[s], hu, lu);
            *reinterpret_cast<uint2*>(st + OBH + r * RSB + c4 * 8) = hu;
            *reinterpret_cast<uint2*>(st + OBL + r * RSB + c4 * 8) = lu;
        }
    };
    auto compute = [&](int buf) {
        const uint32_t stg = sb + buf * STAGE;
        #pragma unroll
        for (int ks = 0; ks < 2; ks++) {
            uint32_t ar = stg + OAH + (uint32_t)(wm * 32 + (l & 15)) * RSA + ks * 32 + (l >> 4) * 16;
            uint32_t ah0[4], ah1[4], al0[4], al1[4];
            LDSM4(ah0, ar);
            LDSM4(ah1, ar + 16 * RSA);
            LDSM4(al0, ar + (OAL - OAH));
            LDSM4(al1, ar + (OAL - OAH) + 16 * RSA);
            #pragma unroll
            for (int jp = 0; jp < 4; jp++) {   // four n16 groups -> 8 n8 atoms
                uint32_t br = stg + OBH + (uint32_t)(ks * 16 + (l & 15)) * RSB
                            + (uint32_t)(wn * 64 + jp * 16 + (l >> 4) * 8) * 2;
                uint32_t bh[4], bl[4];
                LDSM4T(bh, br);
                LDSM4T(bl, br + (OBL - OBH));
                #pragma unroll
                for (int jj = 0; jj < 2; jj++) {
                    const int j = jp * 2 + jj;
                    MMA16816(c[0][j], ah0, bh[2*jj], bh[2*jj+1]);   // hh
                    MMA16816(c[1][j], ah1, bh[2*jj], bh[2*jj+1]);
                    MMA16816(c[0][j], ah0, bl[2*jj], bl[2*jj+1]);   // hl
                    MMA16816(c[1][j], ah1, bl[2*jj], bl[2*jj+1]);
                    MMA16816(c[0][j], al0, bh[2*jj], bh[2*jj+1]);   // lh
                    MMA16816(c[1][j], al1, bh[2*jj], bh[2*jj+1]);
                }
            }
        }
    };

    // -------- pipeline: one __syncthreads per iteration --------
    loadA(0); loadB(0);
    storeStage(0);
    if (NCH > 1) { loadA(32); loadB(32); }
    __syncthreads();

    for (int ch = 0; ch < NCH; ch++) {
        // store next chunk (regs -> other buffer) interleaved with this MMA burst
        if (ch + 1 < NCH) storeStage((ch + 1) & 1);
        compute(ch & 1);
        if (ch + 2 < NCH) { loadA((ch + 2) * 32); loadB((ch + 2) * 32); }
        __syncthreads();
    }

    // -------- epilogue --------
    #pragma unroll
    for (int i = 0; i < 2; i++) {
        const int r0 = wm * 32 + i * 16 + (l >> 2);
        #pragma unroll
        for (int j = 0; j < 8; j++) {
            const int col = wn * 64 + j * 8 + (l & 3) * 2;
            float2 v0 = make_float2(c[i][j][0], c[i][j][1]);
            float2 v1 = make_float2(c[i][j][2], c[i][j][3]);
            if (BIAS_RELU) {
                const float b0 = bias_s[col], b1 = bias_s[col + 1];
                v0.x = fmaxf(v0.x + b0, 0.0f); v0.y = fmaxf(v0.y + b1, 0.0f);
                v1.x = fmaxf(v1.x + b0, 0.0f); v1.y = fmaxf(v1.y + b1, 0.0f);
            }
            *reinterpret_cast<float2*>(Cg + (size_t)r0 * NH + col)       = v0;
            *reinterpret_cast<float2*>(Cg + (size_t)(r0 + 8) * NH + col) = v1;
        }
    }
}

// ===========================================================================
// Launch: GEMM-1 (x@W -> support, fp32) then GEMM-2 (relu(adj@support + b))
// ===========================================================================
extern "C" void kernel_launch(void* const* d_in, const int* in_sizes, int n_in,
                              void* d_out, int out_size)
{
    const float* x   = (const float*)d_in[0];
    const float* adj = (const float*)d_in[1];
    const float* W   = (const float*)d_in[2];
    const float* b   = (const float*)d_in[3];
    float* out = (float*)d_out;

    float* support = nullptr;
    cudaGetSymbolAddress((void**)&support, g_support);

    cudaFuncSetAttribute(mma_gemm_kernel<NF, false>,
                         cudaFuncAttributeMaxDynamicSharedMemorySize, SMEMB);
    cudaFuncSetAttribute(mma_gemm_kernel<NN, true>,
                         cudaFuncAttributeMaxDynamicSharedMemorySize, SMEMB);

    // GEMM-1: support = x @ W    (x as flat [32768, 128], W shared)
    mma_gemm_kernel<NF, false><<<dim3(NB * NN / 128, 1), 256, SMEMB>>>(
        x, NF, 0L, W, 0L, support, 0L, nullptr);

    // GEMM-2: out = relu(adj @ support + b)
    mma_gemm_kernel<NN, true><<<dim3(NN / 128, NB), 256, SMEMB>>>(
        adj, NN, (long)NN * NN, support, (long)NN * NH, out, (long)NN * NH, b);
}

// round 9
// speedup vs baseline: 1.2822x; 1.1748x over previous
#include <cuda_runtime.h>
#include <cuda_fp16.h>
#include <cstdint>

// Problem constants
#define NB   32      // batch
#define NN   1024    // nodes per graph
#define NF   128     // in features
#define NH   128     // hidden features

// fp32 scratch for support = x @ W (static -> allocation-guard safe)
__device__ float g_support[(size_t)NB * NN * NH];   // 16 MB

// ===========================================================================
// PTX helpers (baseline sm_80-class instructions -> compile on compute_103)
// ===========================================================================
__device__ __forceinline__ uint32_t smem_to_u32(const void* p) {
    uint32_t a;
    asm("{ .reg .u64 t; cvta.to.shared.u64 t, %1; cvt.u32.u64 %0, t; }" : "=r"(a) : "l"(p));
    return a;
}

#define LDSM4(R, addr) \
    asm volatile("ldmatrix.sync.aligned.m8n8.x4.shared.b16 {%0,%1,%2,%3}, [%4];" \
        : "=r"((R)[0]), "=r"((R)[1]), "=r"((R)[2]), "=r"((R)[3]) : "r"(addr))

#define LDSM4T(R, addr) \
    asm volatile("ldmatrix.sync.aligned.m8n8.x4.trans.shared.b16 {%0,%1,%2,%3}, [%4];" \
        : "=r"((R)[0]), "=r"((R)[1]), "=r"((R)[2]), "=r"((R)[3]) : "r"(addr))

#define MMA16816(C, A, b0, b1) \
    asm volatile("mma.sync.aligned.m16n8k16.row.col.f32.f16.f16.f32 " \
        "{%0,%1,%2,%3},{%4,%5,%6,%7},{%8,%9},{%0,%1,%2,%3};" \
        : "+f"((C)[0]), "+f"((C)[1]), "+f"((C)[2]), "+f"((C)[3]) \
        : "r"((A)[0]), "r"((A)[1]), "r"((A)[2]), "r"((A)[3]), "r"(b0), "r"(b1))

__device__ __forceinline__ uint32_t pack_h2(__half a, __half b) {
    __half2 t = __halves2half2(a, b);
    return *reinterpret_cast<uint32_t*>(&t);
}

// fp32 -> (hi fp16, lo fp16) split of a float4
__device__ __forceinline__ void split4(float4 v, uint2& hu, uint2& lu) {
    __half h0 = __float2half_rn(v.x), h1 = __float2half_rn(v.y);
    __half h2 = __float2half_rn(v.z), h3 = __float2half_rn(v.w);
    __half l0 = __float2half_rn(v.x - __half2float(h0));
    __half l1 = __float2half_rn(v.y - __half2float(h1));
    __half l2 = __float2half_rn(v.z - __half2float(h2));
    __half l3 = __float2half_rn(v.w - __half2float(h3));
    hu.x = pack_h2(h0, h1); hu.y = pack_h2(h2, h3);
    lu.x = pack_h2(l0, l1); lu.y = pack_h2(l2, l3);
}

// ===========================================================================
// Split-fp16 HMMA GEMM: C = [relu(] A(fp32, MxK) @ B(fp32, Kx128) [+bias)]
//   CTA: 128x128 tile, 512 threads = 16 warps (4m x 4n), warp tile 32x32.
//   4 warps/SMSP for latency hiding; NO occupancy/register cap (the round-6
//   failure was __launch_bounds__(512,2) forcing a 64-reg spill, not the
//   16-warp layout). Accum = 32 regs/thread; total ~100 regs -> no spills.
//   BK=32, double-buffered fp16 smem, single-sync pipelined schedule.
//   MMA stream ordered pass-major per B-group: accumulator RAW reuse
//   distance = 4 MMAs; both B fragment pairs prefetched before the burst.
//   3-pass error-compensated fp16: Ah*Bh + Ah*Bl + Al*Bh, fp32 accumulate.
// ===========================================================================
#define RSA   80        // A smem row stride bytes (32+8 halves)
#define RSB   272       // B smem row stride bytes (128+8 halves)
#define OAH   0
#define OAL   10240     // 128*80
#define OBH   20480
#define OBL   29184     // +32*272
#define STAGE 37888
#define SMEMB (2*STAGE + 512)

template <int K, bool BIAS_RELU>
__global__ __launch_bounds__(512, 1)
void mma_gemm_kernel(const float* __restrict__ A, long lda, long strideAb,
                     const float* __restrict__ B, long strideBb,
                     float* __restrict__ C, long strideCb,
                     const float* __restrict__ bias)
{
    extern __shared__ char smem[];
    constexpr int NCH = K / 32;

    const int tid = threadIdx.x;
    const int l   = tid & 31;
    const int wid = tid >> 5;      // 0..15
    const int wm  = wid >> 2;      // 0..3
    const int wn  = wid & 3;       // 0..3

    const float* Ag = A + (size_t)blockIdx.y * strideAb + (size_t)blockIdx.x * 128 * lda;
    const float* Bg = B + (size_t)blockIdx.y * strideBb;
    float*       Cg = C + (size_t)blockIdx.y * strideCb + (size_t)blockIdx.x * 128 * NH;

    float* bias_s = reinterpret_cast<float*>(smem + 2 * STAGE);
    if (BIAS_RELU && tid < NH) bias_s[tid] = bias[tid];

    const uint32_t sb = smem_to_u32(smem);

    float c[2][4][4];               // [m16 atom][n8 atom][quad]
    #pragma unroll
    for (int i = 0; i < 2; i++)
        #pragma unroll
        for (int j = 0; j < 4; j++)
            #pragma unroll
            for (int q = 0; q < 4; q++) c[i][j][q] = 0.0f;

    float4 pa[2], pb[2];            // register prefetch: 128x32 A + 32x128 B chunk

    auto loadA = [&](int k0) {
        #pragma unroll
        for (int s = 0; s < 2; s++) {
            int f = s * 512 + tid;
            int r = f >> 3, c4 = f & 7;
            pa[s] = *reinterpret_cast<const float4*>(Ag + (size_t)r * lda + k0 + c4 * 4);
        }
    };
    auto loadB = [&](int k0) {
        #pragma unroll
        for (int s = 0; s < 2; s++) {
            int f = s * 512 + tid;
            int r = f >> 5, c4 = f & 31;
            pb[s] = *reinterpret_cast<const float4*>(Bg + (size_t)(k0 + r) * NH + c4 * 4);
        }
    };
    auto storeStage = [&](int buf) {
        char* st = smem + buf * STAGE;
        #pragma unroll
        for (int s = 0; s < 2; s++) {
            int f = s * 512 + tid;
            int r = f >> 3, c4 = f & 7;
            uint2 hu, lu; split4(pa[s], hu, lu);
            *reinterpret_cast<uint2*>(st + OAH + r * RSA + c4 * 8) = hu;
            *reinterpret_cast<uint2*>(st + OAL + r * RSA + c4 * 8) = lu;
        }
        #pragma unroll
        for (int s = 0; s < 2; s++) {
            int f = s * 512 + tid;
            int r = f >> 5, c4 = f & 31;
            uint2 hu, lu; split4(pb[s], hu, lu);
            *reinterpret_cast<uint2*>(st + OBH + r * RSB + c4 * 8) = hu;
            *reinterpret_cast<uint2*>(st + OBL + r * RSB + c4 * 8) = lu;
        }
    };
    auto compute = [&](int buf) {
        const uint32_t stg = sb + buf * STAGE;
        #pragma unroll
        for (int ks = 0; ks < 2; ks++) {
            // A fragments (hi & lo) for this warp's two m16 atoms
            uint32_t ar = stg + OAH + (uint32_t)(wm * 32 + (l & 15)) * RSA + ks * 32 + (l >> 4) * 16;
            uint32_t ah0[4], ah1[4], al0[4], al1[4];
            LDSM4(ah0, ar);
            LDSM4(ah1, ar + 16 * RSA);
            LDSM4(al0, ar + (OAL - OAH));
            LDSM4(al1, ar + (OAL - OAH) + 16 * RSA);
            // Prefetch BOTH n16 B fragment groups (hi & lo) before the burst
            uint32_t bh[2][4], bl[2][4];
            #pragma unroll
            for (int jp = 0; jp < 2; jp++) {
                uint32_t br = stg + OBH + (uint32_t)(ks * 16 + (l & 15)) * RSB
                            + (uint32_t)(wn * 32 + jp * 16 + (l >> 4) * 8) * 2;
                LDSM4T(bh[jp], br);
                LDSM4T(bl[jp], br + (OBL - OBH));
            }
            // MMA burst: pass-major so each accumulator's RAW distance = 4
            #pragma unroll
            for (int jp = 0; jp < 2; jp++) {
                const int j0 = jp * 2, j1 = jp * 2 + 1;
                // hh
                MMA16816(c[0][j0], ah0, bh[jp][0], bh[jp][1]);
                MMA16816(c[1][j0], ah1, bh[jp][0], bh[jp][1]);
                MMA16816(c[0][j1], ah0, bh[jp][2], bh[jp][3]);
                MMA16816(c[1][j1], ah1, bh[jp][2], bh[jp][3]);
                // hl
                MMA16816(c[0][j0], ah0, bl[jp][0], bl[jp][1]);
                MMA16816(c[1][j0], ah1, bl[jp][0], bl[jp][1]);
                MMA16816(c[0][j1], ah0, bl[jp][2], bl[jp][3]);
                MMA16816(c[1][j1], ah1, bl[jp][2], bl[jp][3]);
                // lh
                MMA16816(c[0][j0], al0, bh[jp][0], bh[jp][1]);
                MMA16816(c[1][j0], al1, bh[jp][0], bh[jp][1]);
                MMA16816(c[0][j1], al0, bh[jp][2], bh[jp][3]);
                MMA16816(c[1][j1], al1, bh[jp][2], bh[jp][3]);
            }
        }
    };

    // -------- pipeline: one __syncthreads per iteration --------
    loadA(0); loadB(0);
    storeStage(0);
    if (NCH > 1) { loadA(32); loadB(32); }
    __syncthreads();

    for (int ch = 0; ch < NCH; ch++) {
        // store next chunk (regs -> other buffer) interleaved with this MMA burst
        if (ch + 1 < NCH) storeStage((ch + 1) & 1);
        compute(ch & 1);
        if (ch + 2 < NCH) { loadA((ch + 2) * 32); loadB((ch + 2) * 32); }
        __syncthreads();
    }

    // -------- epilogue --------
    #pragma unroll
    for (int i = 0; i < 2; i++) {
        const int r0 = wm * 32 + i * 16 + (l >> 2);
        #pragma unroll
        for (int j = 0; j < 4; j++) {
            const int col = wn * 32 + j * 8 + (l & 3) * 2;
            float2 v0 = make_float2(c[i][j][0], c[i][j][1]);
            float2 v1 = make_float2(c[i][j][2], c[i][j][3]);
            if (BIAS_RELU) {
                const float b0 = bias_s[col], b1 = bias_s[col + 1];
                v0.x = fmaxf(v0.x + b0, 0.0f); v0.y = fmaxf(v0.y + b1, 0.0f);
                v1.x = fmaxf(v1.x + b0, 0.0f); v1.y = fmaxf(v1.y + b1, 0.0f);
            }
            *reinterpret_cast<float2*>(Cg + (size_t)r0 * NH + col)       = v0;
            *reinterpret_cast<float2*>(Cg + (size_t)(r0 + 8) * NH + col) = v1;
        }
    }
}

// ===========================================================================
// Launch: GEMM-1 (x@W -> support, fp32) then GEMM-2 (relu(adj@support + b))
// ===========================================================================
extern "C" void kernel_launch(void* const* d_in, const int* in_sizes, int n_in,
                              void* d_out, int out_size)
{
    const float* x   = (const float*)d_in[0];
    const float* adj = (const float*)d_in[1];
    const float* W   = (const float*)d_in[2];
    const float* b   = (const float*)d_in[3];
    float* out = (float*)d_out;

    float* support = nullptr;
    cudaGetSymbolAddress((void**)&support, g_support);

    cudaFuncSetAttribute(mma_gemm_kernel<NF, false>,
                         cudaFuncAttributeMaxDynamicSharedMemorySize, SMEMB);
    cudaFuncSetAttribute(mma_gemm_kernel<NN, true>,
                         cudaFuncAttributeMaxDynamicSharedMemorySize, SMEMB);

    // GEMM-1: support = x @ W    (x as flat [32768, 128], W shared)
    mma_gemm_kernel<NF, false><<<dim3(NB * NN / 128, 1), 512, SMEMB>>>(
        x, NF, 0L, W, 0L, support, 0L, nullptr);

    // GEMM-2: out = relu(adj @ support + b)
    mma_gemm_kernel<NN, true><<<dim3(NN / 128, NB), 512, SMEMB>>>(
        adj, NN, (long)NN * NN, support, (long)NN * NH, out, (long)NN * NH, b);
}

// round 11
// speedup vs baseline: 1.5465x; 1.2061x over previous
#include <cuda_runtime.h>
#include <cuda_fp16.h>
#include <cstdint>

// Problem constants
#define NB   32      // batch
#define NN   1024    // nodes per graph
#define NF   128     // in features
#define NH   128     // hidden features

// fp32 scratch for support = x @ W (static -> allocation-guard safe)
__device__ float g_support[(size_t)NB * NN * NH];   // 16 MB

// ===========================================================================
// PTX helpers (baseline sm_80-class instructions -> compile on compute_103)
// ===========================================================================
__device__ __forceinline__ uint32_t smem_to_u32(const void* p) {
    uint32_t a;
    asm("{ .reg .u64 t; cvta.to.shared.u64 t, %1; cvt.u32.u64 %0, t; }" : "=r"(a) : "l"(p));
    return a;
}

#define LDSM4(R, addr) \
    asm volatile("ldmatrix.sync.aligned.m8n8.x4.shared.b16 {%0,%1,%2,%3}, [%4];" \
        : "=r"((R)[0]), "=r"((R)[1]), "=r"((R)[2]), "=r"((R)[3]) : "r"(addr))

#define LDSM4T(R, addr) \
    asm volatile("ldmatrix.sync.aligned.m8n8.x4.trans.shared.b16 {%0,%1,%2,%3}, [%4];" \
        : "=r"((R)[0]), "=r"((R)[1]), "=r"((R)[2]), "=r"((R)[3]) : "r"(addr))

#define MMA16816(C, A, b0, b1) \
    asm volatile("mma.sync.aligned.m16n8k16.row.col.f32.f16.f16.f32 " \
        "{%0,%1,%2,%3},{%4,%5,%6,%7},{%8,%9},{%0,%1,%2,%3};" \
        : "+f"((C)[0]), "+f"((C)[1]), "+f"((C)[2]), "+f"((C)[3]) \
        : "r"((A)[0]), "r"((A)[1]), "r"((A)[2]), "r"((A)[3]), "r"(b0), "r"(b1))

__device__ __forceinline__ uint32_t pack_h2(__half a, __half b) {
    __half2 t = __halves2half2(a, b);
    return *reinterpret_cast<uint32_t*>(&t);
}

// fp32 -> (hi fp16, lo fp16) split of a float4
__device__ __forceinline__ void split4(float4 v, uint2& hu, uint2& lu) {
    __half h0 = __float2half_rn(v.x), h1 = __float2half_rn(v.y);
    __half h2 = __float2half_rn(v.z), h3 = __float2half_rn(v.w);
    __half l0 = __float2half_rn(v.x - __half2float(h0));
    __half l1 = __float2half_rn(v.y - __half2float(h1));
    __half l2 = __float2half_rn(v.z - __half2float(h2));
    __half l3 = __float2half_rn(v.w - __half2float(h3));
    hu.x = pack_h2(h0, h1); hu.y = pack_h2(h2, h3);
    lu.x = pack_h2(l0, l1); lu.y = pack_h2(l2, l3);
}

// fp32 -> hi fp16 only (for the A operand when the Al pass is dropped)
__device__ __forceinline__ void split4hi(float4 v, uint2& hu) {
    hu.x = pack_h2(__float2half_rn(v.x), __float2half_rn(v.y));
    hu.y = pack_h2(__float2half_rn(v.z), __float2half_rn(v.w));
}

// ===========================================================================
// Split-fp16 HMMA GEMM: C = [relu(] A(fp32, MxK) @ B(fp32, Kx128) [+bias)]
//   CTA: 128x128 tile, 512 threads = 16 warps (4m x 4n), warp tile 32x32.
//   BK=32, double-buffered fp16 smem, single-sync pipelined schedule.
//   A3 = true : 3-pass  Ah*Bh + Ah*Bl + Al*Bh  (used for GEMM-1, K=128)
//   A3 = false: 2-pass  Ah*Bh + Ah*Bl          (GEMM-2; A = adj, whose fp16
//              rounding residual contributes only ~1e-4 aggregate rel err,
//              10x inside the 1e-3 tolerance). Cuts MMA stream by 1/3 and
//              removes all A-lo CVT/STS/LDSM work.
// ===========================================================================
#define RSA   80        // A smem row stride bytes (32+8 halves)
#define RSB   272       // B smem row stride bytes (128+8 halves)
#define OAH   0
#define OAL   10240     // 128*80
#define OBH   20480
#define OBL   29184     // +32*272
#define STAGE 37888
#define SMEMB (2*STAGE + 512)

template <int K, bool BIAS_RELU, bool A3>
__global__ __launch_bounds__(512, 1)
void mma_gemm_kernel(const float* __restrict__ A, long lda, long strideAb,
                     const float* __restrict__ B, long strideBb,
                     float* __restrict__ C, long strideCb,
                     const float* __restrict__ bias)
{
    extern __shared__ char smem[];
    constexpr int NCH = K / 32;

    const int tid = threadIdx.x;
    const int l   = tid & 31;
    const int wid = tid >> 5;      // 0..15
    const int wm  = wid >> 2;      // 0..3
    const int wn  = wid & 3;       // 0..3

    const float* Ag = A + (size_t)blockIdx.y * strideAb + (size_t)blockIdx.x * 128 * lda;
    const float* Bg = B + (size_t)blockIdx.y * strideBb;
    float*       Cg = C + (size_t)blockIdx.y * strideCb + (size_t)blockIdx.x * 128 * NH;

    float* bias_s = reinterpret_cast<float*>(smem + 2 * STAGE);
    if (BIAS_RELU && tid < NH) bias_s[tid] = bias[tid];

    const uint32_t sb = smem_to_u32(smem);

    float c[2][4][4];               // [m16 atom][n8 atom][quad]
    #pragma unroll
    for (int i = 0; i < 2; i++)
        #pragma unroll
        for (int j = 0; j < 4; j++)
            #pragma unroll
            for (int q = 0; q < 4; q++) c[i][j][q] = 0.0f;

    float4 pa[2], pb[2];            // register prefetch: 128x32 A + 32x128 B chunk

    auto loadA = [&](int k0) {
        #pragma unroll
        for (int s = 0; s < 2; s++) {
            int f = s * 512 + tid;
            int r = f >> 3, c4 = f & 7;
            pa[s] = *reinterpret_cast<const float4*>(Ag + (size_t)r * lda + k0 + c4 * 4);
        }
    };
    auto loadB = [&](int k0) {
        #pragma unroll
        for (int s = 0; s < 2; s++) {
            int f = s * 512 + tid;
            int r = f >> 5, c4 = f & 31;
            pb[s] = *reinterpret_cast<const float4*>(Bg + (size_t)(k0 + r) * NH + c4 * 4);
        }
    };
    auto storeStage = [&](int buf) {
        char* st = smem + buf * STAGE;
        #pragma unroll
        for (int s = 0; s < 2; s++) {
            int f = s * 512 + tid;
            int r = f >> 3, c4 = f & 7;
            if (A3) {
                uint2 hu, lu; split4(pa[s], hu, lu);
                *reinterpret_cast<uint2*>(st + OAH + r * RSA + c4 * 8) = hu;
                *reinterpret_cast<uint2*>(st + OAL + r * RSA + c4 * 8) = lu;
            } else {
                uint2 hu; split4hi(pa[s], hu);
                *reinterpret_cast<uint2*>(st + OAH + r * RSA + c4 * 8) = hu;
            }
        }
        #pragma unroll
        for (int s = 0; s < 2; s++) {
            int f = s * 512 + tid;
            int r = f >> 5, c4 = f & 31;
            uint2 hu, lu; split4(pb[s], hu, lu);
            *reinterpret_cast<uint2*>(st + OBH + r * RSB + c4 * 8) = hu;
            *reinterpret_cast<uint2*>(st + OBL + r * RSB + c4 * 8) = lu;
        }
    };
    auto compute = [&](int buf) {
        const uint32_t stg = sb + buf * STAGE;
        #pragma unroll
        for (int ks = 0; ks < 2; ks++) {
            // A fragments for this warp's two m16 atoms (hi always; lo only if A3)
            uint32_t ar = stg + OAH + (uint32_t)(wm * 32 + (l & 15)) * RSA + ks * 32 + (l >> 4) * 16;
            uint32_t ah0[4], ah1[4], al0[4], al1[4];
            LDSM4(ah0, ar);
            LDSM4(ah1, ar + 16 * RSA);
            if (A3) {
                LDSM4(al0, ar + (OAL - OAH));
                LDSM4(al1, ar + (OAL - OAH) + 16 * RSA);
            }
            // Prefetch BOTH n16 B fragment groups (hi & lo) before the burst
            uint32_t bh[2][4], bl[2][4];
            #pragma unroll
            for (int jp = 0; jp < 2; jp++) {
                uint32_t br = stg + OBH + (uint32_t)(ks * 16 + (l & 15)) * RSB
                            + (uint32_t)(wn * 32 + jp * 16 + (l >> 4) * 8) * 2;
                LDSM4T(bh[jp], br);
                LDSM4T(bl[jp], br + (OBL - OBH));
            }
            // MMA burst: pass-major so each accumulator's RAW distance = 4
            #pragma unroll
            for (int jp = 0; jp < 2; jp++) {
                const int j0 = jp * 2, j1 = jp * 2 + 1;
                // hh
                MMA16816(c[0][j0], ah0, bh[jp][0], bh[jp][1]);
                MMA16816(c[1][j0], ah1, bh[jp][0], bh[jp][1]);
                MMA16816(c[0][j1], ah0, bh[jp][2], bh[jp][3]);
                MMA16816(c[1][j1], ah1, bh[jp][2], bh[jp][3]);
                // hl
                MMA16816(c[0][j0], ah0, bl[jp][0], bl[jp][1]);
                MMA16816(c[1][j0], ah1, bl[jp][0], bl[jp][1]);
                MMA16816(c[0][j1], ah0, bl[jp][2], bl[jp][3]);
                MMA16816(c[1][j1], ah1, bl[jp][2], bl[jp][3]);
                // lh (only in 3-pass mode)
                if (A3) {
                    MMA16816(c[0][j0], al0, bh[jp][0], bh[jp][1]);
                    MMA16816(c[1][j0], al1, bh[jp][0], bh[jp][1]);
                    MMA16816(c[0][j1], al0, bh[jp][2], bh[jp][3]);
                    MMA16816(c[1][j1], al1, bh[jp][2], bh[jp][3]);
                }
            }
        }
    };

    // -------- pipeline: one __syncthreads per iteration --------
    loadA(0); loadB(0);
    storeStage(0);
    if (NCH > 1) { loadA(32); loadB(32); }
    __syncthreads();

    for (int ch = 0; ch < NCH; ch++) {
        // store next chunk (regs -> other buffer) interleaved with this MMA burst
        if (ch + 1 < NCH) storeStage((ch + 1) & 1);
        compute(ch & 1);
        if (ch + 2 < NCH) { loadA((ch + 2) * 32); loadB((ch + 2) * 32); }
        __syncthreads();
    }

    // -------- epilogue --------
    #pragma unroll
    for (int i = 0; i < 2; i++) {
        const int r0 = wm * 32 + i * 16 + (l >> 2);
        #pragma unroll
        for (int j = 0; j < 4; j++) {
            const int col = wn * 32 + j * 8 + (l & 3) * 2;
            float2 v0 = make_float2(c[i][j][0], c[i][j][1]);
            float2 v1 = make_float2(c[i][j][2], c[i][j][3]);
            if (BIAS_RELU) {
                const float b0 = bias_s[col], b1 = bias_s[col + 1];
                v0.x = fmaxf(v0.x + b0, 0.0f); v0.y = fmaxf(v0.y + b1, 0.0f);
                v1.x = fmaxf(v1.x + b0, 0.0f); v1.y = fmaxf(v1.y + b1, 0.0f);
            }
            *reinterpret_cast<float2*>(Cg + (size_t)r0 * NH + col)       = v0;
            *reinterpret_cast<float2*>(Cg + (size_t)(r0 + 8) * NH + col) = v1;
        }
    }
}

// ===========================================================================
// Launch: GEMM-1 (x@W -> support, 3-pass) then GEMM-2 (relu(adj@support+b), 2-pass)
// ===========================================================================
extern "C" void kernel_launch(void* const* d_in, const int* in_sizes, int n_in,
                              void* d_out, int out_size)
{
    const float* x   = (const float*)d_in[0];
    const float* adj = (const float*)d_in[1];
    const float* W   = (const float*)d_in[2];
    const float* b   = (const float*)d_in[3];
    float* out = (float*)d_out;

    float* support = nullptr;
    cudaGetSymbolAddress((void**)&support, g_support);

    cudaFuncSetAttribute(mma_gemm_kernel<NF, false, true>,
                         cudaFuncAttributeMaxDynamicSharedMemorySize, SMEMB);
    cudaFuncSetAttribute(mma_gemm_kernel<NN, true, false>,
                         cudaFuncAttributeMaxDynamicSharedMemorySize, SMEMB);

    // GEMM-1: support = x @ W    (x as flat [32768, 128], W shared; 3-pass)
    mma_gemm_kernel<NF, false, true><<<dim3(NB * NN / 128, 1), 512, SMEMB>>>(
        x, NF, 0L, W, 0L, support, 0L, nullptr);

    // GEMM-2: out = relu(adj @ support + b)   (2-pass: adj-lo dropped)
    mma_gemm_kernel<NN, true, false><<<dim3(NN / 128, NB), 512, SMEMB>>>(
        adj, NN, (long)NN * NN, support, (long)NN * NH, out, (long)NN * NH, b);
}

// round 12
// speedup vs baseline: 1.6942x; 1.0955x over previous
#include <cuda_runtime.h>
#include <cuda_fp16.h>
#include <cstdint>

// Problem constants
#define NB   32      // batch
#define NN   1024    // nodes per graph
#define NF   128     // in features
#define NH   128     // hidden features

// fp32 scratch for support = x @ W (static -> allocation-guard safe)
__device__ float g_support[(size_t)NB * NN * NH];   // 16 MB

// ===========================================================================
// PTX helpers (baseline sm_80-class instructions -> compile on compute_103)
// ===========================================================================
__device__ __forceinline__ uint32_t smem_to_u32(const void* p) {
    uint32_t a;
    asm("{ .reg .u64 t; cvta.to.shared.u64 t, %1; cvt.u32.u64 %0, t; }" : "=r"(a) : "l"(p));
    return a;
}

#define LDSM4(R, addr) \
    asm volatile("ldmatrix.sync.aligned.m8n8.x4.shared.b16 {%0,%1,%2,%3}, [%4];" \
        : "=r"((R)[0]), "=r"((R)[1]), "=r"((R)[2]), "=r"((R)[3]) : "r"(addr))

#define LDSM4T(R, addr) \
    asm volatile("ldmatrix.sync.aligned.m8n8.x4.trans.shared.b16 {%0,%1,%2,%3}, [%4];" \
        : "=r"((R)[0]), "=r"((R)[1]), "=r"((R)[2]), "=r"((R)[3]) : "r"(addr))

#define MMA16816(C, A, b0, b1) \
    asm volatile("mma.sync.aligned.m16n8k16.row.col.f32.f16.f16.f32 " \
        "{%0,%1,%2,%3},{%4,%5,%6,%7},{%8,%9},{%0,%1,%2,%3};" \
        : "+f"((C)[0]), "+f"((C)[1]), "+f"((C)[2]), "+f"((C)[3]) \
        : "r"((A)[0]), "r"((A)[1]), "r"((A)[2]), "r"((A)[3]), "r"(b0), "r"(b1))

__device__ __forceinline__ uint32_t pack_h2(__half a, __half b) {
    __half2 t = __halves2half2(a, b);
    return *reinterpret_cast<uint32_t*>(&t);
}

// fp32 -> (hi fp16, lo fp16) split of a float4
__device__ __forceinline__ void split4(float4 v, uint2& hu, uint2& lu) {
    __half h0 = __float2half_rn(v.x), h1 = __float2half_rn(v.y);
    __half h2 = __float2half_rn(v.z), h3 = __float2half_rn(v.w);
    __half l0 = __float2half_rn(v.x - __half2float(h0));
    __half l1 = __float2half_rn(v.y - __half2float(h1));
    __half l2 = __float2half_rn(v.z - __half2float(h2));
    __half l3 = __float2half_rn(v.w - __half2float(h3));
    hu.x = pack_h2(h0, h1); hu.y = pack_h2(h2, h3);
    lu.x = pack_h2(l0, l1); lu.y = pack_h2(l2, l3);
}

// fp32 -> hi fp16 only
__device__ __forceinline__ void split4hi(float4 v, uint2& hu) {
    hu.x = pack_h2(__float2half_rn(v.x), __float2half_rn(v.y));
    hu.y = pack_h2(__float2half_rn(v.z), __float2half_rn(v.w));
}

// ===========================================================================
// Split-fp16 HMMA GEMM: C = [relu(] A(fp32, MxK) @ B(fp32, Kx128) [+bias)]
//   CTA: 128x128 tile, 512 threads = 16 warps (4m x 4n), warp tile 32x32.
//   BK=32, double-buffered fp16 smem, single-sync pipelined schedule.
//   PASSES = 3:  Ah*Bh + Ah*Bl + Al*Bh   (GEMM-1, K=128: keeps support exact)
//   PASSES = 2:  Ah*Bh + Ah*Bl
//   PASSES = 1:  Ah*Bh                   (GEMM-2: measured dA-residual error
//                was 1.8e-4; symmetric dB residual adds ~2e-4 -> combined
//                ~2.7e-4, 4x inside the 1e-3 tolerance. Halves the MMA
//                stream again and removes all B-lo CVT/STS/LDSM work.)
// ===========================================================================
#define RSA   80        // A smem row stride bytes (32+8 halves)
#define RSB   272       // B smem row stride bytes (128+8 halves)
#define OAH   0
#define OAL   10240     // 128*80
#define OBH   20480
#define OBL   29184     // +32*272
#define STAGE 37888
#define SMEMB (2*STAGE + 512)

template <int K, bool BIAS_RELU, int PASSES>
__global__ __launch_bounds__(512, 1)
void mma_gemm_kernel(const float* __restrict__ A, long lda, long strideAb,
                     const float* __restrict__ B, long strideBb,
                     float* __restrict__ C, long strideCb,
                     const float* __restrict__ bias)
{
    extern __shared__ char smem[];
    constexpr int NCH = K / 32;
    constexpr bool USE_AL = (PASSES >= 3);
    constexpr bool USE_BL = (PASSES >= 2);

    const int tid = threadIdx.x;
    const int l   = tid & 31;
    const int wid = tid >> 5;      // 0..15
    const int wm  = wid >> 2;      // 0..3
    const int wn  = wid & 3;       // 0..3

    const float* Ag = A + (size_t)blockIdx.y * strideAb + (size_t)blockIdx.x * 128 * lda;
    const float* Bg = B + (size_t)blockIdx.y * strideBb;
    float*       Cg = C + (size_t)blockIdx.y * strideCb + (size_t)blockIdx.x * 128 * NH;

    float* bias_s = reinterpret_cast<float*>(smem + 2 * STAGE);
    if (BIAS_RELU && tid < NH) bias_s[tid] = bias[tid];

    const uint32_t sb = smem_to_u32(smem);

    float c[2][4][4];               // [m16 atom][n8 atom][quad]
    #pragma unroll
    for (int i = 0; i < 2; i++)
        #pragma unroll
        for (int j = 0; j < 4; j++)
            #pragma unroll
            for (int q = 0; q < 4; q++) c[i][j][q] = 0.0f;

    float4 pa[2], pb[2];            // register prefetch: 128x32 A + 32x128 B chunk

    auto loadA = [&](int k0) {
        #pragma unroll
        for (int s = 0; s < 2; s++) {
            int f = s * 512 + tid;
            int r = f >> 3, c4 = f & 7;
            pa[s] = *reinterpret_cast<const float4*>(Ag + (size_t)r * lda + k0 + c4 * 4);
        }
    };
    auto loadB = [&](int k0) {
        #pragma unroll
        for (int s = 0; s < 2; s++) {
            int f = s * 512 + tid;
            int r = f >> 5, c4 = f & 31;
            pb[s] = *reinterpret_cast<const float4*>(Bg + (size_t)(k0 + r) * NH + c4 * 4);
        }
    };
    auto storeStage = [&](int buf) {
        char* st = smem + buf * STAGE;
        #pragma unroll
        for (int s = 0; s < 2; s++) {
            int f = s * 512 + tid;
            int r = f >> 3, c4 = f & 7;
            if (USE_AL) {
                uint2 hu, lu; split4(pa[s], hu, lu);
                *reinterpret_cast<uint2*>(st + OAH + r * RSA + c4 * 8) = hu;
                *reinterpret_cast<uint2*>(st + OAL + r * RSA + c4 * 8) = lu;
            } else {
                uint2 hu; split4hi(pa[s], hu);
                *reinterpret_cast<uint2*>(st + OAH + r * RSA + c4 * 8) = hu;
            }
        }
        #pragma unroll
        for (int s = 0; s < 2; s++) {
            int f = s * 512 + tid;
            int r = f >> 5, c4 = f & 31;
            if (USE_BL) {
                uint2 hu, lu; split4(pb[s], hu, lu);
                *reinterpret_cast<uint2*>(st + OBH + r * RSB + c4 * 8) = hu;
                *reinterpret_cast<uint2*>(st + OBL + r * RSB + c4 * 8) = lu;
            } else {
                uint2 hu; split4hi(pb[s], hu);
                *reinterpret_cast<uint2*>(st + OBH + r * RSB + c4 * 8) = hu;
            }
        }
    };
    auto compute = [&](int buf) {
        const uint32_t stg = sb + buf * STAGE;
        #pragma unroll
        for (int ks = 0; ks < 2; ks++) {
            // A fragments for this warp's two m16 atoms
            uint32_t ar = stg + OAH + (uint32_t)(wm * 32 + (l & 15)) * RSA + ks * 32 + (l >> 4) * 16;
            uint32_t ah0[4], ah1[4], al0[4], al1[4];
            LDSM4(ah0, ar);
            LDSM4(ah1, ar + 16 * RSA);
            if (USE_AL) {
                LDSM4(al0, ar + (OAL - OAH));
                LDSM4(al1, ar + (OAL - OAH) + 16 * RSA);
            }
            // Prefetch BOTH n16 B fragment groups before the burst
            uint32_t bh[2][4], bl[2][4];
            #pragma unroll
            for (int jp = 0; jp < 2; jp++) {
                uint32_t br = stg + OBH + (uint32_t)(ks * 16 + (l & 15)) * RSB
                            + (uint32_t)(wn * 32 + jp * 16 + (l >> 4) * 8) * 2;
                LDSM4T(bh[jp], br);
                if (USE_BL) LDSM4T(bl[jp], br + (OBL - OBH));
            }
            // MMA burst: pass-major so each accumulator's RAW distance = 4
            #pragma unroll
            for (int jp = 0; jp < 2; jp++) {
                const int j0 = jp * 2, j1 = jp * 2 + 1;
                // hh
                MMA16816(c[0][j0], ah0, bh[jp][0], bh[jp][1]);
                MMA16816(c[1][j0], ah1, bh[jp][0], bh[jp][1]);
                MMA16816(c[0][j1], ah0, bh[jp][2], bh[jp][3]);
                MMA16816(c[1][j1], ah1, bh[jp][2], bh[jp][3]);
                // hl
                if (USE_BL) {
                    MMA16816(c[0][j0], ah0, bl[jp][0], bl[jp][1]);
                    MMA16816(c[1][j0], ah1, bl[jp][0], bl[jp][1]);
                    MMA16816(c[0][j1], ah0, bl[jp][2], bl[jp][3]);
                    MMA16816(c[1][j1], ah1, bl[jp][2], bl[jp][3]);
                }
                // lh
                if (USE_AL) {
                    MMA16816(c[0][j0], al0, bh[jp][0], bh[jp][1]);
                    MMA16816(c[1][j0], al1, bh[jp][0], bh[jp][1]);
                    MMA16816(c[0][j1], al0, bh[jp][2], bh[jp][3]);
                    MMA16816(c[1][j1], al1, bh[jp][2], bh[jp][3]);
                }
            }
        }
    };

    // -------- pipeline: one __syncthreads per iteration --------
    loadA(0); loadB(0);
    storeStage(0);
    if (NCH > 1) { loadA(32); loadB(32); }
    __syncthreads();

    for (int ch = 0; ch < NCH; ch++) {
        // store next chunk (regs -> other buffer) interleaved with this MMA burst
        if (ch + 1 < NCH) storeStage((ch + 1) & 1);
        compute(ch & 1);
        if (ch + 2 < NCH) { loadA((ch + 2) * 32); loadB((ch + 2) * 32); }
        __syncthreads();
    }

    // -------- epilogue --------
    #pragma unroll
    for (int i = 0; i < 2; i++) {
        const int r0 = wm * 32 + i * 16 + (l >> 2);
        #pragma unroll
        for (int j = 0; j < 4; j++) {
            const int col = wn * 32 + j * 8 + (l & 3) * 2;
            float2 v0 = make_float2(c[i][j][0], c[i][j][1]);
            float2 v1 = make_float2(c[i][j][2], c[i][j][3]);
            if (BIAS_RELU) {
                const float b0 = bias_s[col], b1 = bias_s[col + 1];
                v0.x = fmaxf(v0.x + b0, 0.0f); v0.y = fmaxf(v0.y + b1, 0.0f);
                v1.x = fmaxf(v1.x + b0, 0.0f); v1.y = fmaxf(v1.y + b1, 0.0f);
            }
            *reinterpret_cast<float2*>(Cg + (size_t)r0 * NH + col)       = v0;
            *reinterpret_cast<float2*>(Cg + (size_t)(r0 + 8) * NH + col) = v1;
        }
    }
}

// ===========================================================================
// Launch: GEMM-1 (x@W -> support, 3-pass) then GEMM-2 (relu(adj@support+b), 1-pass)
// ===========================================================================
extern "C" void kernel_launch(void* const* d_in, const int* in_sizes, int n_in,
                              void* d_out, int out_size)
{
    const float* x   = (const float*)d_in[0];
    const float* adj = (const float*)d_in[1];
    const float* W   = (const float*)d_in[2];
    const float* b   = (const float*)d_in[3];
    float* out = (float*)d_out;

    float* support = nullptr;
    cudaGetSymbolAddress((void**)&support, g_support);

    cudaFuncSetAttribute(mma_gemm_kernel<NF, false, 3>,
                         cudaFuncAttributeMaxDynamicSharedMemorySize, SMEMB);
    cudaFuncSetAttribute(mma_gemm_kernel<NN, true, 1>,
                         cudaFuncAttributeMaxDynamicSharedMemorySize, SMEMB);

    // GEMM-1: support = x @ W    (x as flat [32768, 128], W shared; 3-pass)
    mma_gemm_kernel<NF, false, 3><<<dim3(NB * NN / 128, 1), 512, SMEMB>>>(
        x, NF, 0L, W, 0L, support, 0L, nullptr);

    // GEMM-2: out = relu(adj @ support + b)   (single-pass fp16)
    mma_gemm_kernel<NN, true, 1><<<dim3(NN / 128, NB), 512, SMEMB>>>(
        adj, NN, (long)NN * NN, support, (long)NN * NH, out, (long)NN * NH, b);
}